// round 1
// baseline (speedup 1.0000x reference)
#include <cuda_runtime.h>
#include <math.h>

#define NPIX  (512*1024)
#define NB    8
#define KBINS 16
#define CBINS 4
#define NACC  (KBINS*CBINS + CBINS)   // 64 p_cl + 4 p_l = 68

__device__ float g_acc[72];

__global__ void nid_init_kernel() {
    int i = threadIdx.x;
    if (i < 72) g_acc[i] = 0.0f;
}

__global__ void __launch_bounds__(128)
nid_main_kernel(const float* __restrict__ cam, const float* __restrict__ lab)
{
    float acc_cl[KBINS*CBINS];
    float acc_l[CBINS];
#pragma unroll
    for (int i = 0; i < KBINS*CBINS; i++) acc_cl[i] = 0.0f;
#pragma unroll
    for (int c = 0; c < CBINS; c++) acc_l[c] = 0.0f;

    const int stride = gridDim.x * blockDim.x;
#pragma unroll 1
    for (int n = blockIdx.x * blockDim.x + threadIdx.x; n < NPIX; n += stride) {
        float SS[KBINS + 1];
        float PlS[CBINS];
#pragma unroll
        for (int k = 0; k <= KBINS; k++) SS[k] = 0.0f;
#pragma unroll
        for (int c = 0; c < CBINS; c++) PlS[c] = 0.0f;

#pragma unroll
        for (int b = 0; b < NB; b++) {
            // ---- camera gray ----
            const float* cb = cam + (size_t)b * 3 * NPIX + n;
            float gray = (cb[0] + cb[NPIX] + cb[2 * NPIX]) * (1.0f / 3.0f);

            // ---- label soft-argmax (beta = 500) ----
            const float* lbp = lab + (size_t)b * 4 * NPIX + n;
            float l0 = lbp[0];
            float l1 = lbp[NPIX];
            float l2 = lbp[2 * NPIX];
            float l3 = lbp[3 * NPIX];
            float m  = fmaxf(fmaxf(l0, l1), fmaxf(l2, l3));
            float e0 = __expf((l0 - m) * 500.0f);
            float e1 = __expf((l1 - m) * 500.0f);
            float e2 = __expf((l2 - m) * 500.0f);
            float e3 = __expf((l3 - m) * 500.0f);
            float esum = e0 + e1 + e2 + e3 + 1e-12f;
            float labv = __fdividef(fmaf(3.0f, e3, fmaf(2.0f, e2, e1)), esum);

            // ---- label histogram: exactly one non-saturated edge sigmoid ----
            // PI_l(c) = S(c) - S(c+1), S(c) = sigmoid((labv - (c-0.5))*1000)
            // labv in [0,3]; only edge nearest (labv+0.5) is non-saturated in fp32.
            float u  = labv + 0.5f;
            float ce = rintf(u);                      // edge index 0..4
            float x  = (u - ce) * 1000.0f;            // |x| <= 500
            float sg = __fdividef(1.0f, 1.0f + __expf(-x));
            int   ic = (int)ce;
#pragma unroll
            for (int c = 0; c < CBINS; c++) {
                float addv = (ic == c) ? sg : ((ic == c + 1) ? (1.0f - sg) : 0.0f);
                PlS[c] += addv;
            }

            // ---- camera edge sigmoids: S(k) = sigmoid((gray - k/16)*200) ----
            float a0 = gray * 200.0f;
#pragma unroll
            for (int k = 0; k <= KBINS; k++) {
                // exp(12.5k - 200*gray); overflow->inf->S=0, underflow->0->S=1: both correct
                float e = __expf(fmaf(12.5f, (float)k, -a0));
                SS[k] += __fdividef(1.0f, 1.0f + e);
            }
        }

        // Pc_n[k] = SS[k] - SS[k+1]; outer-product accumulate into p_cl
#pragma unroll
        for (int k = 0; k < KBINS; k++) {
            float pc = SS[k] - SS[k + 1];
#pragma unroll
            for (int c = 0; c < CBINS; c++)
                acc_cl[k * CBINS + c] = fmaf(pc, PlS[c], acc_cl[k * CBINS + c]);
        }
#pragma unroll
        for (int c = 0; c < CBINS; c++) acc_l[c] += PlS[c];
    }

    // ---- reduction: warp shuffle -> shared -> global atomics ----
    __shared__ float red[4][NACC];
    unsigned lane = threadIdx.x & 31u;
    unsigned wrp  = threadIdx.x >> 5;

#pragma unroll
    for (int i = 0; i < KBINS*CBINS; i++) {
        float v = acc_cl[i];
        v += __shfl_down_sync(0xffffffffu, v, 16);
        v += __shfl_down_sync(0xffffffffu, v, 8);
        v += __shfl_down_sync(0xffffffffu, v, 4);
        v += __shfl_down_sync(0xffffffffu, v, 2);
        v += __shfl_down_sync(0xffffffffu, v, 1);
        if (lane == 0) red[wrp][i] = v;
    }
#pragma unroll
    for (int c = 0; c < CBINS; c++) {
        float v = acc_l[c];
        v += __shfl_down_sync(0xffffffffu, v, 16);
        v += __shfl_down_sync(0xffffffffu, v, 8);
        v += __shfl_down_sync(0xffffffffu, v, 4);
        v += __shfl_down_sync(0xffffffffu, v, 2);
        v += __shfl_down_sync(0xffffffffu, v, 1);
        if (lane == 0) red[wrp][KBINS*CBINS + c] = v;
    }
    __syncthreads();
    if (threadIdx.x < NACC) {
        float s = red[0][threadIdx.x] + red[1][threadIdx.x]
                + red[2][threadIdx.x] + red[3][threadIdx.x];
        atomicAdd(&g_acc[threadIdx.x], s);
    }
}

__global__ void nid_final_kernel(float* __restrict__ out)
{
    if (threadIdx.x != 0 || blockIdx.x != 0) return;

    float pcl[KBINS*CBINS];
    float pl[CBINS];
    float scl = 0.0f, sl = 0.0f;
#pragma unroll
    for (int i = 0; i < KBINS*CBINS; i++) { pcl[i] = g_acc[i]; scl += pcl[i]; }
#pragma unroll
    for (int c = 0; c < CBINS; c++) { pl[c] = g_acc[KBINS*CBINS + c]; sl += pl[c]; }

    float inv_scl = 1.0f / scl;
    float inv_sl  = 1.0f / sl;

    float pc[KBINS];
#pragma unroll
    for (int k = 0; k < KBINS; k++) {
        float s = pcl[k*4+0] + pcl[k*4+1] + pcl[k*4+2] + pcl[k*4+3];
        pc[k] = s * inv_scl;   // row-marginal == normalized p_c (label mass == 1/sample)
    }
#pragma unroll
    for (int c = 0; c < CBINS; c++) pl[c] *= inv_sl;

    float I = 0.0f, H = 0.0f;
#pragma unroll
    for (int k = 0; k < KBINS; k++) {
#pragma unroll
        for (int c = 0; c < CBINS; c++) {
            float p  = pcl[k * CBINS + c] * inv_scl;
            float lp = logf(p + 1e-7f);
            float lo = logf(pc[k] * pl[c] + 1e-7f);
            H -= p * lp;
            I += p * (lp - lo);
        }
    }
    float nid = 1.0f - I / H;
    out[0] = (nid - 0.95f) * 20.0f;
}

extern "C" void kernel_launch(void* const* d_in, const int* in_sizes, int n_in,
                              void* d_out, int out_size)
{
    const float* cam = (const float*)d_in[0];   // (8,3,512,1024) fp32
    const float* lab = (const float*)d_in[1];   // (8,4,512,1024) fp32
    float* out = (float*)d_out;

    nid_init_kernel<<<1, 128>>>();
    // 1024 blocks x 128 threads = 131072 threads, 4 positions each (grid-stride)
    nid_main_kernel<<<1024, 128>>>(cam, lab);
    nid_final_kernel<<<1, 1>>>(out);
}